// round 16
// baseline (speedup 1.0000x reference)
#include <cuda_runtime.h>
#include <cuda_bf16.h>
#include <math.h>
#include <stdint.h>

// ---------------- problem constants ----------------
#define B_    4
#define S_    2048
#define H_    4096
#define E_    8
#define A_    64
#define NTOK  (B_ * S_)       // 8192
#define EA    (E_ * A_)       // 512
#define SCALE 2.0f
#define MAXPE 8192
#define KSPLIT 4

// ---------------- static device scratch ----------------
__device__ __nv_bfloat16 g_G[(size_t)NTOK * EA];             // coef*gelu(down) scattered dense
__device__ __nv_bfloat16 g_Xb[(size_t)NTOK * H_];            // X bf16
__device__ __nv_bfloat16 g_Wdb[(size_t)EA * H_];             // Wd bf16
__device__ __nv_bfloat16 g_Wub[(size_t)E_ * H_ * A_];        // Wu bf16
__device__ float g_part[(size_t)KSPLIT * E_ * MAXPE * A_];   // split-K partials
__device__ int   g_tok[E_ * MAXPE];
__device__ float g_w[E_ * MAXPE];                            // SCALE*weight (0 = pad)
__device__ int   g_cnt[E_];
__device__ int   g_cntp[E_];

// ---------------- helpers ----------------
__device__ __forceinline__ void mma_bf16(float* c, const uint32_t* a, const uint32_t* b) {
    asm volatile(
        "mma.sync.aligned.m16n8k16.row.col.f32.bf16.bf16.f32 "
        "{%0,%1,%2,%3}, {%4,%5,%6,%7}, {%8,%9}, {%0,%1,%2,%3};"
        : "+f"(c[0]), "+f"(c[1]), "+f"(c[2]), "+f"(c[3])
        : "r"(a[0]), "r"(a[1]), "r"(a[2]), "r"(a[3]),
          "r"(b[0]), "r"(b[1]));
}
__device__ __forceinline__ void ldsm4(uint32_t& r0, uint32_t& r1, uint32_t& r2, uint32_t& r3,
                                      uint32_t addr) {
    asm volatile("ldmatrix.sync.aligned.m8n8.x4.shared.b16 {%0,%1,%2,%3}, [%4];"
                 : "=r"(r0), "=r"(r1), "=r"(r2), "=r"(r3) : "r"(addr));
}
__device__ __forceinline__ void cp16(uint32_t dst, const void* src) {
    asm volatile("cp.async.cg.shared.global [%0], [%1], 16;" :: "r"(dst), "l"(src));
}
#define CP_COMMIT()  asm volatile("cp.async.commit_group;")
#define CP_WAIT1()   asm volatile("cp.async.wait_group 1;")
__device__ __forceinline__ uint32_t smem_u32(const void* p) {
    uint32_t a;
    asm("{ .reg .u64 t; cvta.to.shared.u64 t, %1; cvt.u32.u64 %0, t; }" : "=r"(a) : "l"(p));
    return a;
}
__device__ __forceinline__ float gelu_exact(float v) {
    return 0.5f * v * (1.0f + erff(v * 0.70710678118654752440f));
}
__device__ __forceinline__ uint2 f4_to_bf4(float4 v) {
    __nv_bfloat162 p0 = __floats2bfloat162_rn(v.x, v.y);
    __nv_bfloat162 p1 = __floats2bfloat162_rn(v.z, v.w);
    uint2 r;
    r.x = *(uint32_t*)&p0;
    r.y = *(uint32_t*)&p1;
    return r;
}

// ================= merged prep kernel (R15 exact) =================
#define PREP_XB  8192
#define PREP_WDB 512
#define PREP_WUB 512
#define PREP_ZB  1024
#define PREP_GRID (PREP_XB + PREP_WDB + PREP_WUB + PREP_ZB)

__device__ __forceinline__ void conv16(const float* __restrict__ src,
                                       __nv_bfloat16* __restrict__ dst, int blk) {
    size_t i = ((size_t)blk * 256 + threadIdx.x) * 16;
    float4 v0 = *(const float4*)(src + i);
    float4 v1 = *(const float4*)(src + i + 4);
    float4 v2 = *(const float4*)(src + i + 8);
    float4 v3 = *(const float4*)(src + i + 12);
    uint2 a = f4_to_bf4(v0), b = f4_to_bf4(v1), c = f4_to_bf4(v2), d = f4_to_bf4(v3);
    uint4 w0, w1;
    w0.x = a.x; w0.y = a.y; w0.z = b.x; w0.w = b.y;
    w1.x = c.x; w1.y = c.y; w1.z = d.x; w1.w = d.y;
    *(uint4*)(dst + i)     = w0;
    *(uint4*)(dst + i + 8) = w1;
}

__global__ __launch_bounds__(256)
void prep_kernel(const float* __restrict__ x,
                 const float* __restrict__ Wd,
                 const float* __restrict__ Wu) {
    const int b = blockIdx.x;
    if (b < PREP_XB) {
        conv16(x, g_Xb, b);
    } else if (b < PREP_XB + PREP_WDB) {
        conv16(Wd, g_Wdb, b - PREP_XB);
    } else if (b < PREP_XB + PREP_WDB + PREP_WUB) {
        conv16(Wu, g_Wub, b - PREP_XB - PREP_WDB);
    } else {
        size_t i = ((size_t)(b - PREP_XB - PREP_WDB - PREP_WUB) * 256 + threadIdx.x) * 16;
        uint4 z = {0, 0, 0, 0};
        *(uint4*)(g_G + i)     = z;
        *(uint4*)(g_G + i + 8) = z;
    }
}

__global__ void zcnt_kernel() {
    if (threadIdx.x < E_) g_cnt[threadIdx.x] = 0;
}

// ================= router (R15 exact) =================
#define RT_CHUNK 1024
#define RT_TPW   2
#define RT_TPB   16

__global__ __launch_bounds__(256)
void router_kernel(const float* __restrict__ r_all,
                   const float* __restrict__ Wr,
                   float* __restrict__ logits_out) {
    __shared__ float wr_s[E_][RT_CHUNK];
    __shared__ int   s_e[RT_TPB * 2];
    __shared__ float s_wt[RT_TPB * 2];
    __shared__ int   s_tk[RT_TPB * 2];

    const int tid  = threadIdx.x;
    const int lane = tid & 31;
    const int wid  = tid >> 5;
    const int tok0 = blockIdx.x * RT_TPB + wid * RT_TPW;

    float acc[RT_TPW][E_];
    #pragma unroll
    for (int t = 0; t < RT_TPW; t++)
        #pragma unroll
        for (int e = 0; e < E_; e++) acc[t][e] = 0.f;

    for (int c = 0; c < H_ / RT_CHUNK; c++) {
        __syncthreads();
        #pragma unroll
        for (int i = tid; i < E_ * RT_CHUNK / 4; i += 256) {
            int e  = i >> 8;
            int k4 = i & 255;
            float4 v = *(const float4*)(Wr + (size_t)e * H_ + c * RT_CHUNK + k4 * 4);
            *(float4*)&wr_s[e][k4 * 4] = v;
        }
        __syncthreads();
        #pragma unroll
        for (int t = 0; t < RT_TPW; t++) {
            const float4* rv = (const float4*)(r_all + (size_t)(tok0 + t) * H_ + c * RT_CHUNK);
            for (int k4 = lane; k4 < RT_CHUNK / 4; k4 += 32) {
                float4 r4 = rv[k4];
                #pragma unroll
                for (int e = 0; e < E_; e++) {
                    float4 w4 = *(const float4*)&wr_s[e][k4 * 4];
                    acc[t][e] += r4.x * w4.x + r4.y * w4.y + r4.z * w4.z + r4.w * w4.w;
                }
            }
        }
    }
    #pragma unroll
    for (int t = 0; t < RT_TPW; t++)
        #pragma unroll
        for (int e = 0; e < E_; e++)
            #pragma unroll
            for (int s = 16; s; s >>= 1)
                acc[t][e] += __shfl_xor_sync(0xffffffffu, acc[t][e], s);

    if (lane == 0) {
        #pragma unroll
        for (int t = 0; t < RT_TPW; t++) {
            const int n = tok0 + t;
            float v1 = -INFINITY; int i1 = 0;
            #pragma unroll
            for (int e = 0; e < E_; e++) {
                logits_out[(size_t)n * E_ + e] = acc[t][e];
                if (acc[t][e] > v1) { v1 = acc[t][e]; i1 = e; }
            }
            float v2 = -INFINITY; int i2 = 0;
            #pragma unroll
            for (int e = 0; e < E_; e++) {
                if (e == i1) continue;
                if (acc[t][e] > v2) { v2 = acc[t][e]; i2 = e; }
            }
            float e2 = expf(v2 - v1);
            float w1 = 1.0f / (1.0f + e2);
            float w2 = e2 * w1;
            const int li = (wid * RT_TPW + t) * 2;
            s_e[li]     = i1; s_wt[li]     = SCALE * w1; s_tk[li]     = n;
            s_e[li + 1] = i2; s_wt[li + 1] = SCALE * w2; s_tk[li + 1] = n;
        }
    }
    __syncthreads();
    if (tid < E_) {
        const int e = tid;
        int cnt = 0;
        #pragma unroll
        for (int i = 0; i < RT_TPB * 2; i++) cnt += (s_e[i] == e);
        if (cnt) {
            int pos = atomicAdd(&g_cnt[e], cnt);
            for (int i = 0; i < RT_TPB * 2; i++) {
                if (s_e[i] == e) {
                    g_tok[e * MAXPE + pos] = s_tk[i];
                    g_w[e * MAXPE + pos]   = s_wt[i];
                    pos++;
                }
            }
        }
    }
}

// ================= pad buckets (R15 exact) =================
__global__ __launch_bounds__(128)
void pad_kernel() {
    const int e = blockIdx.x;
    const int c = g_cnt[e];
    const int cp = (c + 127) & ~127;
    for (int i = c + threadIdx.x; i < cp; i += 128) {
        g_tok[e * MAXPE + i] = 0;
        g_w[e * MAXPE + i]   = 0.f;
    }
    if (threadIdx.x == 0) g_cntp[e] = cp;
}

// ================= split-K grouped down (R15 exact) =================
#define DM    128
#define DN    64
#define DBK   32
#define DROWB 80
#define DKCH  (H_ / DBK / KSPLIT)
#define DATILE (DM * DROWB)
#define DBTILE (DN * DROWB)
#define DSTAGE (DATILE + DBTILE)
#define DSM_NEED (1024 + 3 * DSTAGE)

__global__ __launch_bounds__(256)
void down_split() {
    const int e  = blockIdx.y;
    const int mt = blockIdx.x;
    if (mt * DM >= g_cntp[e]) return;
    const int z  = blockIdx.z;

    extern __shared__ __align__(16) char sm[];
    int* tok_s = (int*)sm;
    const uint32_t sb = smem_u32(sm) + 1024;

    const int tid  = threadIdx.x;
    const int lane = tid & 31;
    const int wid  = tid >> 5;
    const int wm   = (wid >> 1) * 32;
    const int wn   = (wid & 1) * 32;
    const int base = e * MAXPE + mt * DM;

    if (tid < DM) tok_s[tid] = g_tok[base + tid];
    __syncthreads();

    const int arow = tid >> 1;
    const int aoff = (tid & 1) * 16;
    const __nv_bfloat16* asrc = g_Xb + (size_t)tok_s[arow] * H_ + z * (H_ / KSPLIT) + aoff;
    const int brow = tid >> 2;
    const int boff = (tid & 3) * 8;
    const __nv_bfloat16* bsrc = g_Wdb + (size_t)(e * DN + brow) * H_ + z * (H_ / KSPLIT) + boff;

    #define DSTAGE_TILES(s, kt)                                                      \
        do {                                                                         \
            uint32_t dA = sb + (s) * DSTAGE + (uint32_t)(arow * DROWB + aoff * 2);   \
            cp16(dA,      asrc + (size_t)(kt) * DBK);                                \
            cp16(dA + 16, asrc + (size_t)(kt) * DBK + 8);                            \
            uint32_t dB = sb + (s) * DSTAGE + DATILE                                 \
                          + (uint32_t)(brow * DROWB + boff * 2);                     \
            cp16(dB, bsrc + (size_t)(kt) * DBK);                                     \
        } while (0)

    float c[2][4][4];
    #pragma unroll
    for (int mi = 0; mi < 2; mi++)
        #pragma unroll
        for (int ni = 0; ni < 4; ni++)
            #pragma unroll
            for (int k = 0; k < 4; k++) c[mi][ni][k] = 0.f;

    DSTAGE_TILES(0, 0); CP_COMMIT();
    DSTAGE_TILES(1, 1); CP_COMMIT();

    for (int kt = 0; kt < DKCH; kt++) {
        CP_WAIT1();
        __syncthreads();
        if (kt + 2 < DKCH) {
            const int s = (kt + 2) % 3;
            DSTAGE_TILES(s, kt + 2);
        }
        CP_COMMIT();
        const uint32_t sA = sb + (kt % 3) * DSTAGE;
        const uint32_t sB = sA + DATILE;
        #pragma unroll
        for (int ks = 0; ks < 2; ks++) {
            uint32_t afr[2][4], bfr[4][2];
            #pragma unroll
            for (int mi = 0; mi < 2; mi++) {
                uint32_t addr = sA + (uint32_t)((wm + mi * 16 + (lane & 15)) * DROWB
                                                + ks * 32 + (lane >> 4) * 16);
                ldsm4(afr[mi][0], afr[mi][1], afr[mi][2], afr[mi][3], addr);
            }
            const int grp = lane >> 3, nis = grp >> 1, kh = grp & 1;
            #pragma unroll
            for (int p = 0; p < 2; p++) {
                uint32_t addr = sB + (uint32_t)((wn + (2 * p + nis) * 8 + (lane & 7)) * DROWB
                                                + ks * 32 + kh * 16);
                ldsm4(bfr[2 * p][0], bfr[2 * p][1], bfr[2 * p + 1][0], bfr[2 * p + 1][1], addr);
            }
            #pragma unroll
            for (int mi = 0; mi < 2; mi++)
                #pragma unroll
                for (int ni = 0; ni < 4; ni++)
                    mma_bf16(c[mi][ni], afr[mi], bfr[ni]);
        }
        __syncthreads();
    }

    const int g  = lane >> 2;
    const int tg = lane & 3;
    float* pout = g_part + (size_t)z * (E_ * MAXPE * A_) + (size_t)base * A_;
    #pragma unroll
    for (int mi = 0; mi < 2; mi++) {
        #pragma unroll
        for (int ni = 0; ni < 4; ni++) {
            int r0 = wm + mi * 16 + g;
            int c0 = wn + ni * 8 + 2 * tg;
            #pragma unroll
            for (int h = 0; h < 2; h++) {
                int rr = r0 + h * 8;
                float2 v;
                v.x = c[mi][ni][2 * h + 0];
                v.y = c[mi][ni][2 * h + 1];
                *(float2*)&pout[(size_t)rr * A_ + c0] = v;
            }
        }
    }
}

// ================= reduce (R15 exact) =================
__global__ __launch_bounds__(256)
void reduce_kernel() {
    const int e  = blockIdx.y;
    const int mt = blockIdx.x;
    if (mt * DM >= g_cntp[e]) return;
    const int base = e * MAXPE + mt * DM;
    const size_t zs = (size_t)E_ * MAXPE * A_;

    const int tid = threadIdx.x;
    #pragma unroll
    for (int i = 0; i < 16; i++) {
        int p   = tid + i * 256;
        int row = p >> 5;
        int col = (p & 31) * 2;
        float w = g_w[base + row];
        if (w == 0.f) continue;
        size_t off = (size_t)(base + row) * A_ + col;
        float2 s = *(const float2*)&g_part[off];
        #pragma unroll
        for (int zz = 1; zz < KSPLIT; zz++) {
            float2 q = *(const float2*)&g_part[zz * zs + off];
            s.x += q.x; s.y += q.y;
        }
        float v0 = gelu_exact(s.x) * w;
        float v1 = gelu_exact(s.y) * w;
        __nv_bfloat162 pk = __floats2bfloat162_rn(v0, v1);
        int tokn = g_tok[base + row];
        *(uint32_t*)&g_G[(size_t)tokn * EA + e * 64 + col] = *(uint32_t*)&pk;
    }
}

// ================= dense up kernel: 128x64 tile, warp tile 32x32 =================
// Same fragment/accumulation order per output element as before => bit-identical.
// Smaller accumulator file (32 regs) -> ~64 regs total -> 3-4 CTAs/SM.
#define UBM   128
#define UBN   64
#define UBK   32
#define UROWB 80
#define UATILE (UBM * UROWB)          // 10240
#define UBTILE (UBN * UROWB)          // 5120
#define USTAGE (UATILE + UBTILE)      // 15360
#define USM_NEED (3 * USTAGE)         // 46080

__device__ __forceinline__ void up_stage(uint32_t sbase, int s, int kt,
                                         const __nv_bfloat16* Ag, int n0, int tid) {
    // A: 128 rows x 32 cols from g_G tile
    const int arow = tid >> 1;
    const int aoff = (tid & 1) * 16;
    const __nv_bfloat16* a = Ag + (size_t)arow * EA + kt * UBK + aoff;
    uint32_t dA = sbase + (uint32_t)(s * USTAGE + arow * UROWB + aoff * 2);
    cp16(dA, a);
    cp16(dA + 16, a + 8);
    // B: 64 rows (h) x 32 cols (adapter dims of expert kt>>1)
    const int brow = tid >> 2;
    const int boff = (tid & 3) * 8;
    const int e  = kt >> 1;
    const int ab = (kt & 1) * 32;
    const __nv_bfloat16* b = g_Wub + ((size_t)e * H_ + n0 + brow) * A_ + ab + boff;
    uint32_t dB = sbase + (uint32_t)(s * USTAGE + UATILE + brow * UROWB + boff * 2);
    cp16(dB, b);
}

__global__ __launch_bounds__(256)
void up_kernel(const float* __restrict__ o_all,
               float* __restrict__ out) {
    extern __shared__ __align__(16) char sm[];
    const uint32_t sb = smem_u32(sm);

    const int tid  = threadIdx.x;
    const int lane = tid & 31;
    const int wid  = tid >> 5;
    const int wm   = (wid >> 1) * 32;
    const int wn   = (wid & 1) * 32;
    const int m0   = blockIdx.x * UBM;
    const int n0   = blockIdx.y * UBN;

    float c[2][4][4];
    #pragma unroll
    for (int mi = 0; mi < 2; mi++)
        #pragma unroll
        for (int ni = 0; ni < 4; ni++)
            #pragma unroll
            for (int k = 0; k < 4; k++) c[mi][ni][k] = 0.f;

    const __nv_bfloat16* Ag = g_G + (size_t)m0 * EA;
    const int NK = EA / UBK;           // 16

    up_stage(sb, 0, 0, Ag, n0, tid); CP_COMMIT();
    up_stage(sb, 1, 1, Ag, n0, tid); CP_COMMIT();

    for (int kt = 0; kt < NK; kt++) {
        CP_WAIT1();
        __syncthreads();
        if (kt + 2 < NK) {
            up_stage(sb, (kt + 2) % 3, kt + 2, Ag, n0, tid);
        }
        CP_COMMIT();
        const uint32_t sA = sb + (kt % 3) * USTAGE;
        const uint32_t sB = sA + UATILE;
        #pragma unroll
        for (int ks = 0; ks < 2; ks++) {
            uint32_t afr[2][4], bfr[4][2];
            #pragma unroll
            for (int mi = 0; mi < 2; mi++) {
                uint32_t addr = sA + (uint32_t)((wm + mi * 16 + (lane & 15)) * UROWB
                                                + ks * 32 + (lane >> 4) * 16);
                ldsm4(afr[mi][0], afr[mi][1], afr[mi][2], afr[mi][3], addr);
            }
            const int grp = lane >> 3, nis = grp >> 1, kh = grp & 1;
            #pragma unroll
            for (int p = 0; p < 2; p++) {
                uint32_t addr = sB + (uint32_t)((wn + (2 * p + nis) * 8 + (lane & 7)) * UROWB
                                                + ks * 32 + kh * 16);
                ldsm4(bfr[2 * p][0], bfr[2 * p][1], bfr[2 * p + 1][0], bfr[2 * p + 1][1], addr);
            }
            #pragma unroll
            for (int mi = 0; mi < 2; mi++)
                #pragma unroll
                for (int ni = 0; ni < 4; ni++)
                    mma_bf16(c[mi][ni], afr[mi], bfr[ni]);
        }
        __syncthreads();
    }

    // epilogue: out = o + D over 128x64 tile
    const int g  = lane >> 2;
    const int tg = lane & 3;
    #pragma unroll
    for (int mi = 0; mi < 2; mi++) {
        #pragma unroll
        for (int ni = 0; ni < 4; ni++) {
            int r0 = wm + mi * 16 + g;
            int c0 = wn + ni * 8 + 2 * tg;
            #pragma unroll
            for (int h = 0; h < 2; h++) {
                int rr = r0 + h * 8;
                size_t idx = (size_t)(m0 + rr) * H_ + n0 + c0;
                float2 ov = *(const float2*)(o_all + idx);
                float2 w;
                w.x = ov.x + c[mi][ni][2 * h + 0];
                w.y = ov.y + c[mi][ni][2 * h + 1];
                *(float2*)(out + idx) = w;
            }
        }
    }
}

// ================= launch: dual-stream fork-join (R15 exact topology) =================
extern "C" void kernel_launch(void* const* d_in, const int* in_sizes, int n_in,
                              void* d_out, int out_size) {
    const float* x  = (const float*)d_in[0];
    const float* o  = (const float*)d_in[1];
    const float* r  = (const float*)d_in[2];
    const float* Wr = (const float*)d_in[3];
    const float* Wd = (const float*)d_in[4];
    const float* Wu = (const float*)d_in[5];

    float* out    = (float*)d_out;
    float* logits = out + (size_t)NTOK * H_;

    static cudaStream_t s2 = nullptr;
    static cudaEvent_t evFork = nullptr, evJoin = nullptr;
    if (s2 == nullptr) {
        cudaStreamCreateWithFlags(&s2, cudaStreamNonBlocking);
        cudaEventCreateWithFlags(&evFork, cudaEventDisableTiming);
        cudaEventCreateWithFlags(&evJoin, cudaEventDisableTiming);
        cudaFuncSetAttribute(up_kernel,  cudaFuncAttributeMaxDynamicSharedMemorySize, USM_NEED);
        cudaFuncSetAttribute(down_split, cudaFuncAttributeMaxDynamicSharedMemorySize, DSM_NEED);
    }

    cudaEventRecord(evFork, 0);
    cudaStreamWaitEvent(s2, evFork, 0);
    prep_kernel<<<PREP_GRID, 256, 0, s2>>>(x, Wd, Wu);
    cudaEventRecord(evJoin, s2);

    zcnt_kernel<<<1, 32>>>();
    router_kernel<<<NTOK / RT_TPB, 256>>>(r, Wr, logits);
    pad_kernel<<<E_, 128>>>();

    cudaStreamWaitEvent(0, evJoin, 0);
    down_split<<<dim3(MAXPE / DM, E_, KSPLIT), 256, DSM_NEED>>>();
    reduce_kernel<<<dim3(MAXPE / DM, E_), 256>>>();
    up_kernel<<<dim3(NTOK / UBM, H_ / UBN), 256, USM_NEED>>>(o, out);
}

// round 17
// speedup vs baseline: 1.1010x; 1.1010x over previous
#include <cuda_runtime.h>
#include <cuda_bf16.h>
#include <math.h>
#include <stdint.h>

// ---------------- problem constants ----------------
#define B_    4
#define S_    2048
#define H_    4096
#define E_    8
#define A_    64
#define NTOK  (B_ * S_)       // 8192
#define EA    (E_ * A_)       // 512
#define SCALE 2.0f
#define MAXPE 8192
#define KSPLIT 4

// ---------------- static device scratch (zero-init at load) ----------------
__device__ __nv_bfloat16 g_G[(size_t)NTOK * EA];             // coef*gelu(down) scattered dense
__device__ __nv_bfloat16 g_Xb[(size_t)NTOK * H_];            // X bf16
__device__ __nv_bfloat16 g_Wdb[(size_t)EA * H_];             // Wd bf16
__device__ __nv_bfloat16 g_Wub[(size_t)E_ * H_ * A_];        // Wu bf16
__device__ float g_part[(size_t)KSPLIT * E_ * MAXPE * A_];   // split-K partials
__device__ int   g_tok[E_ * MAXPE];                          // always-valid token ids (init 0)
__device__ float g_w[E_ * MAXPE];                            // SCALE*weight; zeroed by prior call
__device__ int   g_cnt[E_];                                  // zeroed by prior call / static init

// ---------------- helpers ----------------
__device__ __forceinline__ void mma_bf16(float* c, const uint32_t* a, const uint32_t* b) {
    asm volatile(
        "mma.sync.aligned.m16n8k16.row.col.f32.bf16.bf16.f32 "
        "{%0,%1,%2,%3}, {%4,%5,%6,%7}, {%8,%9}, {%0,%1,%2,%3};"
        : "+f"(c[0]), "+f"(c[1]), "+f"(c[2]), "+f"(c[3])
        : "r"(a[0]), "r"(a[1]), "r"(a[2]), "r"(a[3]),
          "r"(b[0]), "r"(b[1]));
}
__device__ __forceinline__ void ldsm4(uint32_t& r0, uint32_t& r1, uint32_t& r2, uint32_t& r3,
                                      uint32_t addr) {
    asm volatile("ldmatrix.sync.aligned.m8n8.x4.shared.b16 {%0,%1,%2,%3}, [%4];"
                 : "=r"(r0), "=r"(r1), "=r"(r2), "=r"(r3) : "r"(addr));
}
__device__ __forceinline__ void cp16(uint32_t dst, const void* src) {
    asm volatile("cp.async.cg.shared.global [%0], [%1], 16;" :: "r"(dst), "l"(src));
}
#define CP_COMMIT()  asm volatile("cp.async.commit_group;")
#define CP_WAIT1()   asm volatile("cp.async.wait_group 1;")
__device__ __forceinline__ uint32_t smem_u32(const void* p) {
    uint32_t a;
    asm("{ .reg .u64 t; cvta.to.shared.u64 t, %1; cvt.u32.u64 %0, t; }" : "=r"(a) : "l"(p));
    return a;
}
__device__ __forceinline__ float gelu_exact(float v) {
    return 0.5f * v * (1.0f + erff(v * 0.70710678118654752440f));
}
__device__ __forceinline__ uint2 f4_to_bf4(float4 v) {
    __nv_bfloat162 p0 = __floats2bfloat162_rn(v.x, v.y);
    __nv_bfloat162 p1 = __floats2bfloat162_rn(v.z, v.w);
    uint2 r;
    r.x = *(uint32_t*)&p0;
    r.y = *(uint32_t*)&p1;
    return r;
}

// ================= merged prep kernel (R15 exact) =================
#define PREP_XB  8192
#define PREP_WDB 512
#define PREP_WUB 512
#define PREP_ZB  1024
#define PREP_GRID (PREP_XB + PREP_WDB + PREP_WUB + PREP_ZB)

__device__ __forceinline__ void conv16(const float* __restrict__ src,
                                       __nv_bfloat16* __restrict__ dst, int blk) {
    size_t i = ((size_t)blk * 256 + threadIdx.x) * 16;
    float4 v0 = *(const float4*)(src + i);
    float4 v1 = *(const float4*)(src + i + 4);
    float4 v2 = *(const float4*)(src + i + 8);
    float4 v3 = *(const float4*)(src + i + 12);
    uint2 a = f4_to_bf4(v0), b = f4_to_bf4(v1), c = f4_to_bf4(v2), d = f4_to_bf4(v3);
    uint4 w0, w1;
    w0.x = a.x; w0.y = a.y; w0.z = b.x; w0.w = b.y;
    w1.x = c.x; w1.y = c.y; w1.z = d.x; w1.w = d.y;
    *(uint4*)(dst + i)     = w0;
    *(uint4*)(dst + i + 8) = w1;
}

__global__ __launch_bounds__(256)
void prep_kernel(const float* __restrict__ x,
                 const float* __restrict__ Wd,
                 const float* __restrict__ Wu) {
    const int b = blockIdx.x;
    if (b < PREP_XB) {
        conv16(x, g_Xb, b);
    } else if (b < PREP_XB + PREP_WDB) {
        conv16(Wd, g_Wdb, b - PREP_XB);
    } else if (b < PREP_XB + PREP_WDB + PREP_WUB) {
        conv16(Wu, g_Wub, b - PREP_XB - PREP_WDB);
    } else {
        size_t i = ((size_t)(b - PREP_XB - PREP_WDB - PREP_WUB) * 256 + threadIdx.x) * 16;
        uint4 z = {0, 0, 0, 0};
        *(uint4*)(g_G + i)     = z;
        *(uint4*)(g_G + i + 8) = z;
    }
}

// ================= router (R15 exact; relies on g_cnt/g_w zeroed at entry) =================
#define RT_CHUNK 1024
#define RT_TPW   2
#define RT_TPB   16

__global__ __launch_bounds__(256)
void router_kernel(const float* __restrict__ r_all,
                   const float* __restrict__ Wr,
                   float* __restrict__ logits_out) {
    __shared__ float wr_s[E_][RT_CHUNK];
    __shared__ int   s_e[RT_TPB * 2];
    __shared__ float s_wt[RT_TPB * 2];
    __shared__ int   s_tk[RT_TPB * 2];

    const int tid  = threadIdx.x;
    const int lane = tid & 31;
    const int wid  = tid >> 5;
    const int tok0 = blockIdx.x * RT_TPB + wid * RT_TPW;

    float acc[RT_TPW][E_];
    #pragma unroll
    for (int t = 0; t < RT_TPW; t++)
        #pragma unroll
        for (int e = 0; e < E_; e++) acc[t][e] = 0.f;

    for (int c = 0; c < H_ / RT_CHUNK; c++) {
        __syncthreads();
        #pragma unroll
        for (int i = tid; i < E_ * RT_CHUNK / 4; i += 256) {
            int e  = i >> 8;
            int k4 = i & 255;
            float4 v = *(const float4*)(Wr + (size_t)e * H_ + c * RT_CHUNK + k4 * 4);
            *(float4*)&wr_s[e][k4 * 4] = v;
        }
        __syncthreads();
        #pragma unroll
        for (int t = 0; t < RT_TPW; t++) {
            const float4* rv = (const float4*)(r_all + (size_t)(tok0 + t) * H_ + c * RT_CHUNK);
            for (int k4 = lane; k4 < RT_CHUNK / 4; k4 += 32) {
                float4 r4 = rv[k4];
                #pragma unroll
                for (int e = 0; e < E_; e++) {
                    float4 w4 = *(const float4*)&wr_s[e][k4 * 4];
                    acc[t][e] += r4.x * w4.x + r4.y * w4.y + r4.z * w4.z + r4.w * w4.w;
                }
            }
        }
    }
    #pragma unroll
    for (int t = 0; t < RT_TPW; t++)
        #pragma unroll
        for (int e = 0; e < E_; e++)
            #pragma unroll
            for (int s = 16; s; s >>= 1)
                acc[t][e] += __shfl_xor_sync(0xffffffffu, acc[t][e], s);

    if (lane == 0) {
        #pragma unroll
        for (int t = 0; t < RT_TPW; t++) {
            const int n = tok0 + t;
            float v1 = -INFINITY; int i1 = 0;
            #pragma unroll
            for (int e = 0; e < E_; e++) {
                logits_out[(size_t)n * E_ + e] = acc[t][e];
                if (acc[t][e] > v1) { v1 = acc[t][e]; i1 = e; }
            }
            float v2 = -INFINITY; int i2 = 0;
            #pragma unroll
            for (int e = 0; e < E_; e++) {
                if (e == i1) continue;
                if (acc[t][e] > v2) { v2 = acc[t][e]; i2 = e; }
            }
            float e2 = expf(v2 - v1);
            float w1 = 1.0f / (1.0f + e2);
            float w2 = e2 * w1;
            const int li = (wid * RT_TPW + t) * 2;
            s_e[li]     = i1; s_wt[li]     = SCALE * w1; s_tk[li]     = n;
            s_e[li + 1] = i2; s_wt[li + 1] = SCALE * w2; s_tk[li + 1] = n;
        }
    }
    __syncthreads();
    if (tid < E_) {
        const int e = tid;
        int cnt = 0;
        #pragma unroll
        for (int i = 0; i < RT_TPB * 2; i++) cnt += (s_e[i] == e);
        if (cnt) {
            int pos = atomicAdd(&g_cnt[e], cnt);
            for (int i = 0; i < RT_TPB * 2; i++) {
                if (s_e[i] == e) {
                    g_tok[e * MAXPE + pos] = s_tk[i];
                    g_w[e * MAXPE + pos]   = s_wt[i];
                    pos++;
                }
            }
        }
    }
}

// ================= split-K grouped down (R15 body, inline pad) =================
#define DM    128
#define DN    64
#define DBK   32
#define DROWB 80
#define DKCH  (H_ / DBK / KSPLIT)
#define DATILE (DM * DROWB)
#define DBTILE (DN * DROWB)
#define DSTAGE (DATILE + DBTILE)
#define DSM_NEED (1024 + 3 * DSTAGE)

__global__ __launch_bounds__(256)
void down_split() {
    const int e  = blockIdx.y;
    const int mt = blockIdx.x;
    const int cp = (g_cnt[e] + 127) & ~127;       // inline pad
    if (mt * DM >= cp) return;
    const int z  = blockIdx.z;

    extern __shared__ __align__(16) char sm[];
    int* tok_s = (int*)sm;
    const uint32_t sb = smem_u32(sm) + 1024;

    const int tid  = threadIdx.x;
    const int lane = tid & 31;
    const int wid  = tid >> 5;
    const int wm   = (wid >> 1) * 32;
    const int wn   = (wid & 1) * 32;
    const int base = e * MAXPE + mt * DM;

    if (tid < DM) tok_s[tid] = g_tok[base + tid];   // pad rows: stale-but-valid token ids
    __syncthreads();

    const int arow = tid >> 1;
    const int aoff = (tid & 1) * 16;
    const __nv_bfloat16* asrc = g_Xb + (size_t)tok_s[arow] * H_ + z * (H_ / KSPLIT) + aoff;
    const int brow = tid >> 2;
    const int boff = (tid & 3) * 8;
    const __nv_bfloat16* bsrc = g_Wdb + (size_t)(e * DN + brow) * H_ + z * (H_ / KSPLIT) + boff;

    #define DSTAGE_TILES(s, kt)                                                      \
        do {                                                                         \
            uint32_t dA = sb + (s) * DSTAGE + (uint32_t)(arow * DROWB + aoff * 2);   \
            cp16(dA,      asrc + (size_t)(kt) * DBK);                                \
            cp16(dA + 16, asrc + (size_t)(kt) * DBK + 8);                            \
            uint32_t dB = sb + (s) * DSTAGE + DATILE                                 \
                          + (uint32_t)(brow * DROWB + boff * 2);                     \
            cp16(dB, bsrc + (size_t)(kt) * DBK);                                     \
        } while (0)

    float c[2][4][4];
    #pragma unroll
    for (int mi = 0; mi < 2; mi++)
        #pragma unroll
        for (int ni = 0; ni < 4; ni++)
            #pragma unroll
            for (int k = 0; k < 4; k++) c[mi][ni][k] = 0.f;

    DSTAGE_TILES(0, 0); CP_COMMIT();
    DSTAGE_TILES(1, 1); CP_COMMIT();

    for (int kt = 0; kt < DKCH; kt++) {
        CP_WAIT1();
        __syncthreads();
        if (kt + 2 < DKCH) {
            const int s = (kt + 2) % 3;
            DSTAGE_TILES(s, kt + 2);
        }
        CP_COMMIT();
        const uint32_t sA = sb + (kt % 3) * DSTAGE;
        const uint32_t sB = sA + DATILE;
        #pragma unroll
        for (int ks = 0; ks < 2; ks++) {
            uint32_t afr[2][4], bfr[4][2];
            #pragma unroll
            for (int mi = 0; mi < 2; mi++) {
                uint32_t addr = sA + (uint32_t)((wm + mi * 16 + (lane & 15)) * DROWB
                                                + ks * 32 + (lane >> 4) * 16);
                ldsm4(afr[mi][0], afr[mi][1], afr[mi][2], afr[mi][3], addr);
            }
            const int grp = lane >> 3, nis = grp >> 1, kh = grp & 1;
            #pragma unroll
            for (int p = 0; p < 2; p++) {
                uint32_t addr = sB + (uint32_t)((wn + (2 * p + nis) * 8 + (lane & 7)) * DROWB
                                                + ks * 32 + kh * 16);
                ldsm4(bfr[2 * p][0], bfr[2 * p][1], bfr[2 * p + 1][0], bfr[2 * p + 1][1], addr);
            }
            #pragma unroll
            for (int mi = 0; mi < 2; mi++)
                #pragma unroll
                for (int ni = 0; ni < 4; ni++)
                    mma_bf16(c[mi][ni], afr[mi], bfr[ni]);
        }
        __syncthreads();
    }

    const int g  = lane >> 2;
    const int tg = lane & 3;
    float* pout = g_part + (size_t)z * (E_ * MAXPE * A_) + (size_t)base * A_;
    #pragma unroll
    for (int mi = 0; mi < 2; mi++) {
        #pragma unroll
        for (int ni = 0; ni < 4; ni++) {
            int r0 = wm + mi * 16 + g;
            int c0 = wn + ni * 8 + 2 * tg;
            #pragma unroll
            for (int h = 0; h < 2; h++) {
                int rr = r0 + h * 8;
                float2 v;
                v.x = c[mi][ni][2 * h + 0];
                v.y = c[mi][ni][2 * h + 1];
                *(float2*)&pout[(size_t)rr * A_ + c0] = v;
            }
        }
    }
}

// ================= reduce (R15 body, inline pad) =================
__global__ __launch_bounds__(256)
void reduce_kernel() {
    const int e  = blockIdx.y;
    const int mt = blockIdx.x;
    const int cp = (g_cnt[e] + 127) & ~127;       // inline pad
    if (mt * DM >= cp) return;
    const int base = e * MAXPE + mt * DM;
    const size_t zs = (size_t)E_ * MAXPE * A_;

    const int tid = threadIdx.x;
    #pragma unroll
    for (int i = 0; i < 16; i++) {
        int p   = tid + i * 256;
        int row = p >> 5;
        int col = (p & 31) * 2;
        float w = g_w[base + row];
        if (w == 0.f) continue;                   // pad rows: w==0 (pre-zeroed buffer)
        size_t off = (size_t)(base + row) * A_ + col;
        float2 s = *(const float2*)&g_part[off];
        #pragma unroll
        for (int zz = 1; zz < KSPLIT; zz++) {
            float2 q = *(const float2*)&g_part[zz * zs + off];
            s.x += q.x; s.y += q.y;
        }
        float v0 = gelu_exact(s.x) * w;
        float v1 = gelu_exact(s.y) * w;
        __nv_bfloat162 pk = __floats2bfloat162_rn(v0, v1);
        int tokn = g_tok[base + row];
        *(uint32_t*)&g_G[(size_t)tokn * EA + e * 64 + col] = *(uint32_t*)&pk;
    }
}

// ================= dense up kernel (R15 exact 128x128) + end-of-call cleanup =================
#define BM   128
#define BN   128
#define BK   32
#define ROWB 80
#define TILEB (BM * ROWB)
#define STAGEB (2 * TILEB)
#define SM_NEED (3 * STAGEB)

__device__ __forceinline__ void stage_tiles(uint32_t sA, uint32_t sB,
                                            const __nv_bfloat16* Asrc, size_t lda,
                                            const __nv_bfloat16* Bsrc, size_t ldb,
                                            int tid) {
    const int row = tid >> 1;
    const int co  = (tid & 1) * 16;
    const uint32_t d = (uint32_t)(row * ROWB + co * 2);
    cp16(sA + d,      Asrc + (size_t)row * lda + co);
    cp16(sA + d + 16, Asrc + (size_t)row * lda + co + 8);
    cp16(sB + d,      Bsrc + (size_t)row * ldb + co);
    cp16(sB + d + 16, Bsrc + (size_t)row * ldb + co + 8);
}

__device__ __forceinline__ void compute_chunk(uint32_t sA, uint32_t sB,
                                              float c[2][8][4],
                                              int wm, int wn, int lane) {
    #pragma unroll
    for (int ks = 0; ks < 2; ks++) {
        uint32_t afr[2][4], bfr[8][2];
        #pragma unroll
        for (int mi = 0; mi < 2; mi++) {
            uint32_t addr = sA + (uint32_t)((wm + mi * 16 + (lane & 15)) * ROWB
                                            + ks * 32 + (lane >> 4) * 16);
            ldsm4(afr[mi][0], afr[mi][1], afr[mi][2], afr[mi][3], addr);
        }
        const int grp = lane >> 3, nis = (grp >> 1), kh = (grp & 1);
        #pragma unroll
        for (int p = 0; p < 4; p++) {
            uint32_t addr = sB + (uint32_t)((wn + (2 * p + nis) * 8 + (lane & 7)) * ROWB
                                            + ks * 32 + kh * 16);
            ldsm4(bfr[2 * p][0], bfr[2 * p][1], bfr[2 * p + 1][0], bfr[2 * p + 1][1], addr);
        }
        #pragma unroll
        for (int mi = 0; mi < 2; mi++)
            #pragma unroll
            for (int ni = 0; ni < 8; ni++)
                mma_bf16(c[mi][ni], afr[mi], bfr[ni]);
    }
}

__global__ __launch_bounds__(256, 2)
void up_kernel(const float* __restrict__ o_all,
               float* __restrict__ out) {
    extern __shared__ __align__(16) char sm[];
    const uint32_t sb = smem_u32(sm);

    const int tid  = threadIdx.x;
    const int lane = tid & 31;
    const int wid  = tid >> 5;
    const int wm   = (wid >> 1) * 32;
    const int wn   = (wid & 1) * 64;
    const int m0   = blockIdx.x * BM;
    const int n0   = blockIdx.y * BN;

    // cleanup for next execution: g_w/g_cnt fully consumed by reduce (prior launch).
    // 64 blocks x 256 thr x 4 floats = 65536 = E_*MAXPE.
    if (blockIdx.y == 0) {
        if (blockIdx.x < 64) {
            size_t i = ((size_t)blockIdx.x * 256 + tid) * 4;
            *(float4*)&g_w[i] = make_float4(0.f, 0.f, 0.f, 0.f);
        }
        if (blockIdx.x == 0 && tid < E_) g_cnt[tid] = 0;
    }

    float c[2][8][4];
    #pragma unroll
    for (int mi = 0; mi < 2; mi++)
        #pragma unroll
        for (int ni = 0; ni < 8; ni++)
            #pragma unroll
            for (int k = 0; k < 4; k++) c[mi][ni][k] = 0.f;

    const __nv_bfloat16* Ag = g_G + (size_t)m0 * EA;
    const int NK = EA / BK;

    #define UP_BSRC(kt) (g_Wub + ((size_t)((kt) >> 1) * H_ + n0) * A_ + ((kt) & 1) * 32)

    stage_tiles(sb, sb + TILEB, Ag, EA, UP_BSRC(0), A_, tid);
    CP_COMMIT();
    stage_tiles(sb + STAGEB, sb + STAGEB + TILEB, Ag + BK, EA, UP_BSRC(1), A_, tid);
    CP_COMMIT();

    for (int kt = 0; kt < NK; kt++) {
        CP_WAIT1();
        __syncthreads();
        if (kt + 2 < NK) {
            const int s = (kt + 2) % 3;
            stage_tiles(sb + s * STAGEB, sb + s * STAGEB + TILEB,
                        Ag + (size_t)(kt + 2) * BK, EA,
                        UP_BSRC(kt + 2), A_, tid);
        }
        CP_COMMIT();
        const int b = kt % 3;
        compute_chunk(sb + b * STAGEB, sb + b * STAGEB + TILEB, c, wm, wn, lane);
    }

    const int g  = lane >> 2;
    const int tg = lane & 3;
    #pragma unroll
    for (int mi = 0; mi < 2; mi++) {
        #pragma unroll
        for (int ni = 0; ni < 8; ni++) {
            int r0 = wm + mi * 16 + g;
            int c0 = wn + ni * 8 + 2 * tg;
            #pragma unroll
            for (int h = 0; h < 2; h++) {
                int rr = r0 + h * 8;
                size_t idx = (size_t)(m0 + rr) * H_ + n0 + c0;
                float2 ov = *(const float2*)(o_all + idx);
                float2 w;
                w.x = ov.x + c[mi][ni][2 * h + 0];
                w.y = ov.y + c[mi][ni][2 * h + 1];
                *(float2*)(out + idx) = w;
            }
        }
    }
}

// ================= launch: dual-stream fork-join, 5 kernels =================
extern "C" void kernel_launch(void* const* d_in, const int* in_sizes, int n_in,
                              void* d_out, int out_size) {
    const float* x  = (const float*)d_in[0];
    const float* o  = (const float*)d_in[1];
    const float* r  = (const float*)d_in[2];
    const float* Wr = (const float*)d_in[3];
    const float* Wd = (const float*)d_in[4];
    const float* Wu = (const float*)d_in[5];

    float* out    = (float*)d_out;
    float* logits = out + (size_t)NTOK * H_;

    static cudaStream_t s2 = nullptr;
    static cudaEvent_t evFork = nullptr, evJoin = nullptr;
    if (s2 == nullptr) {
        cudaStreamCreateWithFlags(&s2, cudaStreamNonBlocking);
        cudaEventCreateWithFlags(&evFork, cudaEventDisableTiming);
        cudaEventCreateWithFlags(&evJoin, cudaEventDisableTiming);
        cudaFuncSetAttribute(up_kernel,  cudaFuncAttributeMaxDynamicSharedMemorySize, SM_NEED);
        cudaFuncSetAttribute(down_split, cudaFuncAttributeMaxDynamicSharedMemorySize, DSM_NEED);
    }

    cudaEventRecord(evFork, 0);
    cudaStreamWaitEvent(s2, evFork, 0);
    prep_kernel<<<PREP_GRID, 256, 0, s2>>>(x, Wd, Wu);
    cudaEventRecord(evJoin, s2);

    router_kernel<<<NTOK / RT_TPB, 256>>>(r, Wr, logits);

    cudaStreamWaitEvent(0, evJoin, 0);
    down_split<<<dim3(MAXPE / DM, E_, KSPLIT), 256, DSM_NEED>>>();
    reduce_kernel<<<dim3(MAXPE / DM, E_), 256>>>();
    up_kernel<<<dim3(NTOK / BM, H_ / BN), 256, SM_NEED>>>(o, out);
}